// round 3
// baseline (speedup 1.0000x reference)
#include <cuda_runtime.h>
#include <cstdint>

// Problem constants
#define M_TOTAL 4096            // B*T = 64*64
#define N_TOTAL 128             // LEAVES
#define K_TOTAL 16080           // IN_FEATURES
#define KB 16                   // K per mainloop chunk
#define TOTAL_CHUNKS (K_TOTAL / KB)   // 1005
#define SPLITS 4                // split-K factor -> 32*4 = 128 CTAs
#define MB 128
#define NB 128
#define LDS_STRIDE 20           // padded row stride (floats) -> conflict-free frag loads

// split-K partial accumulators (static device scratch; allocations are banned)
__device__ float g_part[SPLITS * M_TOTAL * N_TOTAL];

__device__ __forceinline__ uint32_t f2tf32(float f) {
    uint32_t r;
    asm("cvt.rna.tf32.f32 %0, %1;" : "=r"(r) : "f"(f));
    return r;
}

__device__ __forceinline__ void cp_async16(uint32_t saddr, const float* gptr) {
    asm volatile("cp.async.cg.shared.global [%0], [%1], 16;\n" :: "r"(saddr), "l"(gptr));
}

template <int N>
__device__ __forceinline__ void cp_wait() {
    asm volatile("cp.async.wait_group %0;\n" :: "n"(N));
}

__device__ __forceinline__ void mma_tf32(float* c, const uint32_t* a, const uint32_t* b) {
    asm volatile(
        "mma.sync.aligned.m16n8k8.row.col.f32.tf32.tf32.f32 "
        "{%0,%1,%2,%3}, {%4,%5,%6,%7}, {%8,%9}, {%0,%1,%2,%3};\n"
        : "+f"(c[0]), "+f"(c[1]), "+f"(c[2]), "+f"(c[3])
        : "r"(a[0]), "r"(a[1]), "r"(a[2]), "r"(a[3]), "r"(b[0]), "r"(b[1]));
}

__global__ __launch_bounds__(256, 1)
void gemm_tf32_kernel(const float* __restrict__ x, const float* __restrict__ W) {
    __shared__ float As[2][MB][LDS_STRIDE];
    __shared__ float Bs[2][NB][LDS_STRIDE];

    const int tid  = threadIdx.x;
    const int lane = tid & 31;
    const int warp = tid >> 5;
    const int wm   = (warp >> 1) * 32;   // warp M origin within CTA tile (4 warps in M)
    const int wn   = (warp & 1) * 64;    // warp N origin within CTA tile (2 warps in N)
    const int g    = lane >> 2;          // mma group id (0..7)
    const int tg   = lane & 3;           // thread-in-group (0..3)

    const int m0    = blockIdx.x * MB;
    const int split = blockIdx.y;
    const int c_begin = (TOTAL_CHUNKS * split) / SPLITS;
    const int c_end   = (TOTAL_CHUNKS * (split + 1)) / SPLITS;
    const int nchunks = c_end - c_begin;

    // Global->shared load assignment: each thread copies 2x16B of A and 2x16B of B.
    const int lrow = tid >> 1;           // 0..127 (row of A tile / row of W tile)
    const int lq   = (tid & 1) * 2;      // quad base within the 16-float row

    const float* gA = x + (size_t)(m0 + lrow) * K_TOTAL;
    const float* gB = W + (size_t)lrow * K_TOTAL;

    const uint32_t sA0 = (uint32_t)__cvta_generic_to_shared(&As[0][lrow][lq * 4]);
    const uint32_t sB0 = (uint32_t)__cvta_generic_to_shared(&Bs[0][lrow][lq * 4]);
    const uint32_t bufBytes = (uint32_t)(MB * LDS_STRIDE * sizeof(float)); // 10240

    float acc[2][8][4];
    #pragma unroll
    for (int i = 0; i < 2; ++i)
        #pragma unroll
        for (int j = 0; j < 8; ++j)
            #pragma unroll
            for (int q = 0; q < 4; ++q) acc[i][j][q] = 0.0f;

    auto issue_chunk = [&](int chunk, int buf) {
        const int koff = (c_begin + chunk) * KB;
        const float* pa = gA + koff + lq * 4;
        const float* pb = gB + koff + lq * 4;
        const uint32_t da = sA0 + (uint32_t)buf * bufBytes;
        const uint32_t db = sB0 + (uint32_t)buf * bufBytes;
        cp_async16(da,      pa);
        cp_async16(da + 16, pa + 4);
        cp_async16(db,      pb);
        cp_async16(db + 16, pb + 4);
        asm volatile("cp.async.commit_group;\n");
    };

    issue_chunk(0, 0);

    for (int c = 0; c < nchunks; ++c) {
        const int buf = c & 1;
        if (c + 1 < nchunks) {
            issue_chunk(c + 1, buf ^ 1);
            cp_wait<1>();
        } else {
            cp_wait<0>();
        }
        __syncthreads();   // chunk c visible to all warps

        const float (*A)[LDS_STRIDE] = As[buf];
        const float (*B)[LDS_STRIDE] = Bs[buf];

        #pragma unroll
        for (int ks = 0; ks < 2; ++ks) {
            const int kc = ks * 8 + tg;
            uint32_t af[2][4];
            #pragma unroll
            for (int i = 0; i < 2; ++i) {
                const int r = wm + i * 16 + g;
                af[i][0] = f2tf32(A[r][kc]);
                af[i][1] = f2tf32(A[r + 8][kc]);
                af[i][2] = f2tf32(A[r][kc + 4]);
                af[i][3] = f2tf32(A[r + 8][kc + 4]);
            }
            uint32_t bf[8][2];
            #pragma unroll
            for (int j = 0; j < 8; ++j) {
                const int n = wn + j * 8 + g;
                bf[j][0] = f2tf32(B[n][kc]);
                bf[j][1] = f2tf32(B[n][kc + 4]);
            }
            #pragma unroll
            for (int i = 0; i < 2; ++i)
                #pragma unroll
                for (int j = 0; j < 8; ++j)
                    mma_tf32(acc[i][j], af[i], bf[j]);
        }
        __syncthreads();   // all warps done with buf before it is refilled
    }

    // Write split partial (no bias here; epilogue adds it once).
    float* gp = g_part + (size_t)split * (M_TOTAL * N_TOTAL) + (size_t)m0 * N_TOTAL;
    #pragma unroll
    for (int i = 0; i < 2; ++i) {
        #pragma unroll
        for (int j = 0; j < 8; ++j) {
            const int r    = wm + i * 16 + g;
            const int cIdx = wn + j * 8 + 2 * tg;
            float2 v0 = make_float2(acc[i][j][0], acc[i][j][1]);
            float2 v1 = make_float2(acc[i][j][2], acc[i][j][3]);
            *(float2*)(gp + (size_t)r * N_TOTAL + cIdx)       = v0;
            *(float2*)(gp + (size_t)(r + 8) * N_TOTAL + cIdx) = v1;
        }
    }
}

// Reduce split-K partials + bias + hardtanh, then fused softmax->Gini epilogue.
__global__ __launch_bounds__(256)
void epilogue_kernel(const float* __restrict__ bias,
                     const float* __restrict__ contrib,
                     float* __restrict__ out) {
    const int idx = blockIdx.x * 256 + threadIdx.x;   // 0 .. 4096*128-1
    const int l  = idx & 127;
    const int bt = idx >> 7;
    const int t  = bt & 63;

    float s = g_part[idx];
    #pragma unroll
    for (int sp = 1; sp < SPLITS; ++sp)
        s += g_part[(size_t)sp * (M_TOTAL * N_TOTAL) + idx];
    s += bias[l];
    s = fminf(1.0f, fmaxf(-1.0f, s));   // Hardtanh

    // contribution[t, l, 0..15]
    const float4* cp4 = (const float4*)(contrib + ((size_t)(t * 128 + l) << 4));
    float z[16];
    float m = -1e30f;
    #pragma unroll
    for (int q = 0; q < 4; ++q) {
        float4 cv = cp4[q];
        z[q * 4 + 0] = s * cv.x;
        z[q * 4 + 1] = s * cv.y;
        z[q * 4 + 2] = s * cv.z;
        z[q * 4 + 3] = s * cv.w;
    }
    #pragma unroll
    for (int c = 0; c < 16; ++c) m = fmaxf(m, z[c]);

    float S = 0.0f, S2 = 0.0f;
    #pragma unroll
    for (int c = 0; c < 16; ++c) {
        float e = __expf(z[c] - m);
        S  += e;
        S2 += e * e;
    }
    const float gini = 16.0f - S2 / (S * S);   // sum_c (1 - p_c^2)

    out[idx] = s;                                // symbolic_paths
    out[(size_t)(M_TOTAL * N_TOTAL) + idx] = gini;  // class_value
}

extern "C" void kernel_launch(void* const* d_in, const int* in_sizes, int n_in,
                              void* d_out, int out_size) {
    const float* x       = (const float*)d_in[0];  // [64,64,16080]
    const float* W       = (const float*)d_in[1];  // [128,16080]
    const float* b       = (const float*)d_in[2];  // [128]
    const float* contrib = (const float*)d_in[3];  // [64,128,16]
    float* out = (float*)d_out;                    // [2,64,64,128] concat

    gemm_tf32_kernel<<<dim3(M_TOTAL / MB, SPLITS), 256>>>(x, W);
    epilogue_kernel<<<(M_TOTAL * N_TOTAL) / 256, 256>>>(b, contrib, out);
}